// round 2
// baseline (speedup 1.0000x reference)
#include <cuda_runtime.h>
#include <cuda_fp16.h>
#include <cstdint>
#include <cstddef>

// ---------------- problem constants ----------------
#define BT_N   4096      // B*T
#define F_DIM  256
#define GV     16384     // G*V
#define V_DIM  8192
#define DG     8
#define KK     768       // 3 * F_DIM  (fp16-split GEMM packed along K)

// ---------------- scratch (device globals; no runtime allocation) ----------------
__device__ float  g_hidden[(size_t)BT_N * GV];          // 256 MB fp32 logits
__device__ __half g_Asplit[(size_t)BT_N * KK];          // [xh | xh | xl]
__device__ __half g_Bsplit[(size_t)GV   * KK];          // [Wh | Wl | Wh]
__device__ float  g_R[BT_N * 2];                        // mask*inv_msum/Z per (bt,g)
__device__ float  g_MX[BT_N * 2];                       // row max of h per (bt,g)
__device__ float  g_marg[GV];                           // marginal accumulator
__device__ float  g_inv_msum;

// ---------------- accurate FFMA-based log (avoid MUFU 2^-22 error for gumbel) ----------------
__device__ __forceinline__ float my_logf(float a) {
    float m, r, s, t, i, f;
    int e;
    e = (__float_as_int(a) - 0x3f2aaaab) & 0xff800000;
    m = __int_as_float(__float_as_int(a) - e);
    i = (float)e * 1.19209290e-7f; // 2^-23
    f = m - 1.0f;
    s = f * f;
    r = -0.130310059f;
    t =  0.140869141f;
    r = fmaf(r, s, -0.121483512f);
    t = fmaf(t, s,  0.139814854f);
    r = fmaf(r, s, -0.166846126f);
    t = fmaf(t, s,  0.200120345f);
    r = fmaf(r, s, -0.249996200f);
    r = fmaf(t, f, r);
    r = fmaf(r, f,  0.333331972f);
    r = fmaf(r, f, -0.500000000f);
    r = fmaf(r, s, f);
    r = fmaf(i, 0.693147182f, r);
    return r;
}

__device__ __forceinline__ float my_expf(float a) {
    float f, r, j;
    int i;
    j = fmaf(1.442695041f, a, 12582912.f) - 12582912.f;
    f = fmaf(j, -6.93145752e-1f, a);
    f = fmaf(j, -1.42860677e-6f, f);
    i = (int)j;
    r = 1.37805939e-3f;
    r = fmaf(r, f, 8.37312452e-3f);
    r = fmaf(r, f, 4.16695364e-2f);
    r = fmaf(r, f, 1.66664720e-1f);
    r = fmaf(r, f, 4.99999851e-1f);
    r = fmaf(r, f, 1.00000000e+0f);
    r = fmaf(r, f, 1.00000000e+0f);
    r = __int_as_float(__float_as_int(r) + (i << 23));
    return r;
}

// ---------------- prep kernels ----------------
__global__ void prep_split_w(const float* __restrict__ W) {
    int idx = blockIdx.x * blockDim.x + threadIdx.x;
    if (idx >= GV * F_DIM) return;
    int n = idx >> 8, k = idx & 255;
    float w = W[idx];
    __half hi = __float2half_rn(w);
    __half lo = __float2half_rn(w - __half2float(hi));
    size_t base = (size_t)n * KK;
    g_Bsplit[base + k]        = hi;
    g_Bsplit[base + 256 + k]  = lo;
    g_Bsplit[base + 512 + k]  = hi;
}

__global__ void prep_split_x(const float* __restrict__ X) {
    int idx = blockIdx.x * blockDim.x + threadIdx.x;
    if (idx >= BT_N * F_DIM) return;
    int n = idx >> 8, k = idx & 255;
    float x = X[idx];
    __half hi = __float2half_rn(x);
    __half lo = __float2half_rn(x - __half2float(hi));
    size_t base = (size_t)n * KK;
    g_Asplit[base + k]        = hi;
    g_Asplit[base + 256 + k]  = hi;
    g_Asplit[base + 512 + k]  = lo;
}

__global__ void prep_misc(const int* __restrict__ mask) {
    int t = threadIdx.x;
    for (int i = t; i < GV; i += 256) g_marg[i] = 0.f;
    int s = 0;
    for (int i = t; i < BT_N; i += 256) s += mask[i];
    __shared__ int sm[256];
    sm[t] = s; __syncthreads();
    for (int o = 128; o; o >>= 1) { if (t < o) sm[t] += sm[t + o]; __syncthreads(); }
    if (t == 0) g_inv_msum = 1.0f / (float)sm[0];
}

// ---------------- GEMM: hidden = A' * B'^T + bias ----------------
// M=4096, N=16384, K=768, fp16 in / fp32 acc, 128x128 block tile, BK=64, 3 stages
#define BM 128
#define BN 128
#define BK 64
#define STAGES 3
#define STAGE_A_BYTES (BM * BK * 2)
#define STAGE_BYTES   (2 * STAGE_A_BYTES)
#define GEMM_SMEM     (STAGES * STAGE_BYTES)

__global__ void __launch_bounds__(256, 1) gemm_kernel(const float* __restrict__ bias) {
    extern __shared__ __align__(128) char smem[];
    int tid  = threadIdx.x;
    int lane = tid & 31, warp = tid >> 5;
    int wm = warp >> 2, wn = warp & 3;        // 2 x 4 warp grid, warp tile 64x32
    int bm = blockIdx.y, bn = blockIdx.x;
    const __half* gA = g_Asplit + (size_t)bm * BM * KK;
    const __half* gB = g_Bsplit + (size_t)bn * BN * KK;

    auto load_stage = [&](int s, int kt) {
        int k0 = kt * BK;
        char* sa = smem + s * STAGE_BYTES;
        char* sb = sa + STAGE_A_BYTES;
        #pragma unroll
        for (int i = 0; i < 4; i++) {
            int idx = tid + 256 * i;       // 0..1023
            int row = idx >> 3;            // 0..127
            int c16 = idx & 7;             // 16B chunk within 128B row
            int pc  = c16 ^ (row & 7);     // xor swizzle
            uint32_t da = (uint32_t)__cvta_generic_to_shared(sa + row * 128 + pc * 16);
            const __half* srcA = gA + (size_t)row * KK + k0 + c16 * 8;
            asm volatile("cp.async.cg.shared.global [%0], [%1], 16;\n" :: "r"(da), "l"(srcA));
            uint32_t db = (uint32_t)__cvta_generic_to_shared(sb + row * 128 + pc * 16);
            const __half* srcB = gB + (size_t)row * KK + k0 + c16 * 8;
            asm volatile("cp.async.cg.shared.global [%0], [%1], 16;\n" :: "r"(db), "l"(srcB));
        }
    };

    float acc[4][4][4];
    #pragma unroll
    for (int a = 0; a < 4; a++)
        #pragma unroll
        for (int b = 0; b < 4; b++)
            #pragma unroll
            for (int c = 0; c < 4; c++) acc[a][b][c] = 0.f;

    const int NKT = KK / BK;  // 12
    #pragma unroll
    for (int kt = 0; kt < STAGES - 1; kt++) {
        load_stage(kt, kt);
        asm volatile("cp.async.commit_group;\n");
    }

    #pragma unroll 1
    for (int kt = 0; kt < NKT; kt++) {
        asm volatile("cp.async.wait_group 1;\n");
        __syncthreads();
        int pf = kt + STAGES - 1;
        if (pf < NKT) load_stage(pf % STAGES, pf);
        asm volatile("cp.async.commit_group;\n");

        int s = kt % STAGES;
        const char* sa = smem + s * STAGE_BYTES;
        const char* sb = sa + STAGE_A_BYTES;
        #pragma unroll
        for (int kk = 0; kk < 4; kk++) {  // 4 k16-steps within BK=64
            uint32_t a[4][4], b[4][2];
            #pragma unroll
            for (int mt = 0; mt < 4; mt++) {
                int row = wm * 64 + mt * 16 + (lane & 15);
                int c16 = kk * 2 + (lane >> 4);
                int pc  = c16 ^ (row & 7);
                uint32_t addr = (uint32_t)__cvta_generic_to_shared(sa + row * 128 + pc * 16);
                asm volatile("ldmatrix.sync.aligned.m8n8.x4.shared.b16 {%0,%1,%2,%3}, [%4];\n"
                    : "=r"(a[mt][0]), "=r"(a[mt][1]), "=r"(a[mt][2]), "=r"(a[mt][3]) : "r"(addr));
            }
            #pragma unroll
            for (int nt2 = 0; nt2 < 2; nt2++) {
                int row = wn * 32 + nt2 * 16 + (lane & 15);
                int c16 = kk * 2 + (lane >> 4);
                int pc  = c16 ^ (row & 7);
                uint32_t addr = (uint32_t)__cvta_generic_to_shared(sb + row * 128 + pc * 16);
                uint32_t r0, r1, r2, r3;
                asm volatile("ldmatrix.sync.aligned.m8n8.x4.shared.b16 {%0,%1,%2,%3}, [%4];\n"
                    : "=r"(r0), "=r"(r1), "=r"(r2), "=r"(r3) : "r"(addr));
                b[nt2 * 2][0]     = r0; b[nt2 * 2 + 1][0] = r1;
                b[nt2 * 2][1]     = r2; b[nt2 * 2 + 1][1] = r3;
            }
            #pragma unroll
            for (int mt = 0; mt < 4; mt++)
                #pragma unroll
                for (int nt = 0; nt < 4; nt++) {
                    asm volatile("mma.sync.aligned.m16n8k16.row.col.f32.f16.f16.f32 "
                        "{%0,%1,%2,%3}, {%4,%5,%6,%7}, {%8,%9}, {%0,%1,%2,%3};\n"
                        : "+f"(acc[mt][nt][0]), "+f"(acc[mt][nt][1]),
                          "+f"(acc[mt][nt][2]), "+f"(acc[mt][nt][3])
                        : "r"(a[mt][0]), "r"(a[mt][1]), "r"(a[mt][2]), "r"(a[mt][3]),
                          "r"(b[nt][0]), "r"(b[nt][1]));
                }
        }
    }

    // epilogue: add bias, write fp32 hidden
    #pragma unroll
    for (int mt = 0; mt < 4; mt++) {
        int row0 = bm * BM + wm * 64 + mt * 16 + (lane >> 2);
        #pragma unroll
        for (int nt = 0; nt < 4; nt++) {
            int col = bn * BN + wn * 32 + nt * 8 + (lane & 3) * 2;
            float b0 = bias[col], b1 = bias[col + 1];
            float* p0 = g_hidden + (size_t)row0 * GV + col;
            float* p1 = g_hidden + (size_t)(row0 + 8) * GV + col;
            p0[0] = acc[mt][nt][0] + b0;
            p0[1] = acc[mt][nt][1] + b1;
            p1[0] = acc[mt][nt][2] + b0;
            p1[1] = acc[mt][nt][3] + b1;
        }
    }
}

// ---------------- row kernel: gumbel softmax + argmax + codevectors + soft-Z ----------------
__global__ void __launch_bounds__(256) row_kernel(
    const float* __restrict__ u, const float* __restrict__ emb,
    const int* __restrict__ mask, float* __restrict__ out)
{
    int r  = blockIdx.x;         // 0..8191  (= bt*2 + g)
    int bt = r >> 1, g = r & 1;
    int t  = threadIdx.x;
    const float* hrow = g_hidden + (size_t)bt * GV + (size_t)g * V_DIM;
    const float* urow = u + (size_t)r * V_DIM;
    const float* erow = emb + (size_t)g * V_DIM * DG;

    float h[32], y[32];
    float mh = -1e30f, my = -1e30f;
    int   bi = 0;
    #pragma unroll
    for (int i = 0; i < 32; i++) {
        int v = i * 256 + t;
        float hv = hrow[v];
        float uu = fmaxf(urow[v], 1.17549435e-38f);
        float inner = -my_logf(uu);
        float gum   = -my_logf(inner);
        float yv = hv + gum;
        h[i] = hv; y[i] = yv;
        mh = fmaxf(mh, hv);
        if (yv > my) { my = yv; bi = v; }
    }

    __shared__ float s1[256];
    __shared__ int   s2[256];

    // block max of h
    s1[t] = mh; __syncthreads();
    for (int o = 128; o; o >>= 1) { if (t < o) s1[t] = fmaxf(s1[t], s1[t + o]); __syncthreads(); }
    mh = s1[0]; __syncthreads();

    // block argmax of y (ties -> lower index, matching argmax-first semantics)
    s1[t] = my; s2[t] = bi; __syncthreads();
    for (int o = 128; o; o >>= 1) {
        if (t < o) {
            float ov = s1[t + o]; int oi = s2[t + o];
            if (ov > s1[t] || (ov == s1[t] && oi < s2[t])) { s1[t] = ov; s2[t] = oi; }
        }
        __syncthreads();
    }
    my = s1[0];
    int amax = s2[0];
    __syncthreads();

    // exp sums
    float sh = 0.f, sy = 0.f;
    #pragma unroll
    for (int i = 0; i < 32; i++) {
        sh += __expf(h[i] - mh);
        float e = __expf(y[i] - my);
        y[i] = e; sy += e;
    }
    s1[t] = sh; __syncthreads();
    for (int o = 128; o; o >>= 1) { if (t < o) s1[t] += s1[t + o]; __syncthreads(); }
    sh = s1[0]; __syncthreads();
    s1[t] = sy; __syncthreads();
    for (int o = 128; o; o >>= 1) { if (t < o) s1[t] += s1[t + o]; __syncthreads(); }
    sy = s1[0]; __syncthreads();

    // codevectors: cv[d] = sum_v p_v * emb[v][d]
    float cv[8] = {0,0,0,0,0,0,0,0};
    #pragma unroll
    for (int i = 0; i < 32; i++) {
        int v = i * 256 + t;
        const float4* ep = (const float4*)(erow + (size_t)v * DG);
        float4 e0 = ep[0], e1 = ep[1];
        float p = y[i];
        cv[0] = fmaf(p, e0.x, cv[0]); cv[1] = fmaf(p, e0.y, cv[1]);
        cv[2] = fmaf(p, e0.z, cv[2]); cv[3] = fmaf(p, e0.w, cv[3]);
        cv[4] = fmaf(p, e1.x, cv[4]); cv[5] = fmaf(p, e1.y, cv[5]);
        cv[6] = fmaf(p, e1.z, cv[6]); cv[7] = fmaf(p, e1.w, cv[7]);
    }
    #pragma unroll
    for (int d = 0; d < 8; d++)
        for (int o = 16; o; o >>= 1) cv[d] += __shfl_xor_sync(0xffffffffu, cv[d], o);

    __shared__ float scv[8][8];
    int warp = t >> 5, lane = t & 31;
    if (lane == 0) {
        #pragma unroll
        for (int d = 0; d < 8; d++) scv[warp][d] = cv[d];
    }
    __syncthreads();
    if (t < 8) {
        float s = 0.f;
        #pragma unroll
        for (int w = 0; w < 8; w++) s += scv[w][t];
        out[bt * 16 + g * 8 + t] = s / sy;
    }
    if (t == 0) {
        out[65537 + r] = (float)amax;                              // targets_idx
        g_R[r]  = mask[bt] ? (g_inv_msum / sh) : 0.f;
        g_MX[r] = mh;
    }
}

// ---------------- marginal column reduction ----------------
__global__ void __launch_bounds__(256) marg_kernel() {
    int c = blockIdx.x * 256 + threadIdx.x;   // 0..16383 (one g per block)
    int g = c >> 13;
    int bt0 = blockIdx.y * 1024;
    float acc = 0.f;
    for (int bt = bt0; bt < bt0 + 1024; ++bt) {
        int r = bt * 2 + g;
        acc += g_R[r] * __expf(g_hidden[(size_t)bt * GV + c] - g_MX[r]);
    }
    atomicAdd(&g_marg[c], acc);
}

// ---------------- perplexity ----------------
__global__ void __launch_bounds__(256) final_kernel(float* __restrict__ out) {
    int t = threadIdx.x;
    float s0 = 0.f, s1v = 0.f;
    for (int c = t; c < V_DIM; c += 256) {
        float m = g_marg[c];
        s0 += m * my_logf(m + 1e-7f);
    }
    for (int c = V_DIM + t; c < GV; c += 256) {
        float m = g_marg[c];
        s1v += m * my_logf(m + 1e-7f);
    }
    __shared__ float sa[256], sb[256];
    sa[t] = s0; sb[t] = s1v; __syncthreads();
    for (int o = 128; o; o >>= 1) {
        if (t < o) { sa[t] += sa[t + o]; sb[t] += sb[t + o]; }
        __syncthreads();
    }
    if (t == 0) out[65536] = my_expf(-sa[0]) + my_expf(-sb[0]);
}

// ---------------- launch ----------------
extern "C" void kernel_launch(void* const* d_in, const int* in_sizes, int n_in,
                              void* d_out, int out_size) {
    const float* x    = (const float*)d_in[0];   // [8,512,256]
    const float* u    = (const float*)d_in[1];   // [8192, 8192]
    const float* emb  = (const float*)d_in[2];   // [1, 16384, 8]
    const float* W    = (const float*)d_in[3];   // [16384, 256]
    const float* bias = (const float*)d_in[4];   // [16384]
    const int*   mask = (const int*)d_in[5];     // [8,512]
    float* out = (float*)d_out;

    cudaFuncSetAttribute(gemm_kernel, cudaFuncAttributeMaxDynamicSharedMemorySize, GEMM_SMEM);

    prep_split_w<<<(GV * F_DIM + 255) / 256, 256>>>(W);
    prep_split_x<<<(BT_N * F_DIM + 255) / 256, 256>>>(x);
    prep_misc<<<1, 256>>>(mask);

    dim3 ggrid(GV / BN, BT_N / BM);   // (128, 32)
    gemm_kernel<<<ggrid, 256, GEMM_SMEM>>>(bias);

    row_kernel<<<BT_N * 2, 256>>>(u, emb, mask, out);

    dim3 mgrid(GV / 256, 4);
    marg_kernel<<<mgrid, 256>>>();

    final_kernel<<<1, 256>>>(out);
}